// round 1
// baseline (speedup 1.0000x reference)
#include <cuda_runtime.h>
#include <cuda_bf16.h>
#include <cstdint>
#include <math.h>

// ----------------------------------------------------------------------------
// MLP: out[e] = gelu_tanh(x[e] @ w1[e]) @ w2[e]
//   E=8, T=2048, H=1024, F=4096, fp32 in/out.
// Strategy: bf16x3 split GEMM on tensor cores (mma.sync m16n8k16), fp32 acc.
//   a = a_hi + a_lo (bf16 each); a*b ~= ah*bh + ah*bl + al*bh  (error ~2^-18)
// Block tile 128x128, K-step 32, 8 warps each computing 64x32.
// ----------------------------------------------------------------------------

#define TM 128
#define TN 128
#define TK 32
#define SSTR 40                 // bf16 stride per row; S=20 words -> conflict-free frag loads
#define SZ (128 * SSTR)         // bf16 elems per tile array
#define SMEM_BYTES (8 * SZ * 2) // 4 arrays x 2 stages x SZ x 2B = 81920 B

static constexpr int E_ = 8, T_ = 2048, H_ = 1024, F_ = 4096;

// intermediate h = gelu(x@w1): 8*2048*4096 fp32 = 256 MB static device scratch
__device__ float g_h[(size_t)E_ * T_ * F_];

__device__ __forceinline__ void mma16816(float* c, const uint32_t* a, const uint32_t* b) {
    asm volatile(
        "mma.sync.aligned.m16n8k16.row.col.f32.bf16.bf16.f32 "
        "{%0,%1,%2,%3}, {%4,%5,%6,%7}, {%8,%9}, {%0,%1,%2,%3};\n"
        : "+f"(c[0]), "+f"(c[1]), "+f"(c[2]), "+f"(c[3])
        : "r"(a[0]), "r"(a[1]), "r"(a[2]), "r"(a[3]), "r"(b[0]), "r"(b[1]));
}

__device__ __forceinline__ float gelu_tanh_f(float x) {
    float x3 = x * x * x;
    float inner = 0.7978845608028654f * (x + 0.044715f * x3);
    return 0.5f * x * (1.0f + tanhf(inner));
}

template <bool GELU>
__global__ __launch_bounds__(256, 1)
void gemm_bf16x3(const float* __restrict__ A, const float* __restrict__ B,
                 float* __restrict__ C, int M, int N, int K,
                 long strA, long strB, long strC) {
    extern __shared__ __align__(16) __nv_bfloat16 smem[];

    const int e = blockIdx.z;
    A += (long)e * strA;
    B += (long)e * strB;
    C += (long)e * strC;

    const int mb = blockIdx.y * TM;
    const int nb = blockIdx.x * TN;
    const int tid = threadIdx.x;
    const int warp = tid >> 5, lane = tid & 31;
    const int wm = (warp >> 2) * 64;   // 2 warp rows
    const int wn = (warp & 3) * 32;    // 4 warp cols
    const int g = lane >> 2, q = lane & 3;

    float acc[4][4][4];
#pragma unroll
    for (int mi = 0; mi < 4; mi++)
#pragma unroll
        for (int ni = 0; ni < 4; ni++)
#pragma unroll
            for (int k2 = 0; k2 < 4; k2++) acc[mi][ni][k2] = 0.0f;

    float4 va[4], vb[4];

    // global tile loads (coalesced fp32 float4)
    auto gload = [&](int kt) {
        const float* Ag = A + (long)mb * K + kt * TK;
#pragma unroll
        for (int i = 0; i < 4; i++) {
            int f4 = i * 256 + tid;
            va[i] = *(const float4*)(Ag + (long)(f4 >> 3) * K + (f4 & 7) * 4);
        }
        const float* Bg = B + (long)(kt * TK) * N + nb;
#pragma unroll
        for (int i = 0; i < 4; i++) {
            int f4 = i * 256 + tid;
            vb[i] = *(const float4*)(Bg + (long)(f4 >> 5) * N + (f4 & 31) * 4);
        }
    };

    // split fp32 -> bf16 hi/lo and store tiles to smem (B transposed to [n][k])
    auto sstore = [&](int s) {
        __nv_bfloat16* Ah = smem + (0 + s) * SZ;
        __nv_bfloat16* Al = smem + (2 + s) * SZ;
        __nv_bfloat16* Bh = smem + (4 + s) * SZ;
        __nv_bfloat16* Bl = smem + (6 + s) * SZ;
#pragma unroll
        for (int i = 0; i < 4; i++) {
            int f4 = i * 256 + tid;
            int r = f4 >> 3, k = (f4 & 7) * 4;
            float v[4] = {va[i].x, va[i].y, va[i].z, va[i].w};
            __nv_bfloat16 h[4], l[4];
#pragma unroll
            for (int j = 0; j < 4; j++) {
                h[j] = __float2bfloat16(v[j]);
                l[j] = __float2bfloat16(v[j] - __bfloat162float(h[j]));
            }
            *(__nv_bfloat162*)(Ah + r * SSTR + k)     = __halves2bfloat162(h[0], h[1]);
            *(__nv_bfloat162*)(Ah + r * SSTR + k + 2) = __halves2bfloat162(h[2], h[3]);
            *(__nv_bfloat162*)(Al + r * SSTR + k)     = __halves2bfloat162(l[0], l[1]);
            *(__nv_bfloat162*)(Al + r * SSTR + k + 2) = __halves2bfloat162(l[2], l[3]);
        }
#pragma unroll
        for (int i = 0; i < 4; i++) {
            int f4 = i * 256 + tid;
            int kr = f4 >> 5, c = (f4 & 31) * 4;
            float v[4] = {vb[i].x, vb[i].y, vb[i].z, vb[i].w};
#pragma unroll
            for (int j = 0; j < 4; j++) {
                __nv_bfloat16 h = __float2bfloat16(v[j]);
                __nv_bfloat16 l = __float2bfloat16(v[j] - __bfloat162float(h));
                Bh[(c + j) * SSTR + kr] = h;
                Bl[(c + j) * SSTR + kr] = l;
            }
        }
    };

    auto compute = [&](int s, int kk) {
        const __nv_bfloat16* Ah = smem + (0 + s) * SZ;
        const __nv_bfloat16* Al = smem + (2 + s) * SZ;
        const __nv_bfloat16* Bh = smem + (4 + s) * SZ;
        const __nv_bfloat16* Bl = smem + (6 + s) * SZ;
        uint32_t ah[4][4], al[4][4], bh[4][2], bl[4][2];
#pragma unroll
        for (int mi = 0; mi < 4; mi++) {
            int r = wm + mi * 16 + g;
            const __nv_bfloat16* p  = Ah + r * SSTR + kk + q * 2;
            const __nv_bfloat16* p8 = p + 8 * SSTR;
            ah[mi][0] = *(const uint32_t*)p;
            ah[mi][1] = *(const uint32_t*)p8;
            ah[mi][2] = *(const uint32_t*)(p + 8);
            ah[mi][3] = *(const uint32_t*)(p8 + 8);
            const __nv_bfloat16* pl  = Al + r * SSTR + kk + q * 2;
            const __nv_bfloat16* pl8 = pl + 8 * SSTR;
            al[mi][0] = *(const uint32_t*)pl;
            al[mi][1] = *(const uint32_t*)pl8;
            al[mi][2] = *(const uint32_t*)(pl + 8);
            al[mi][3] = *(const uint32_t*)(pl8 + 8);
        }
#pragma unroll
        for (int ni = 0; ni < 4; ni++) {
            int cI = wn + ni * 8 + g;
            const __nv_bfloat16* p = Bh + cI * SSTR + kk + q * 2;
            bh[ni][0] = *(const uint32_t*)p;
            bh[ni][1] = *(const uint32_t*)(p + 8);
            const __nv_bfloat16* pl = Bl + cI * SSTR + kk + q * 2;
            bl[ni][0] = *(const uint32_t*)pl;
            bl[ni][1] = *(const uint32_t*)(pl + 8);
        }
#pragma unroll
        for (int mi = 0; mi < 4; mi++)
#pragma unroll
            for (int ni = 0; ni < 4; ni++) {
                mma16816(acc[mi][ni], ah[mi], bh[ni]);
                mma16816(acc[mi][ni], ah[mi], bl[ni]);
                mma16816(acc[mi][ni], al[mi], bh[ni]);
            }
    };

    const int NK = K / TK;
    gload(0);
    sstore(0);
    __syncthreads();

    for (int kt = 0; kt < NK; kt++) {
        int s = kt & 1;
        if (kt + 1 < NK) gload(kt + 1);     // overlap next-tile GMEM with compute
        compute(s, 0);
        compute(s, 16);
        if (kt + 1 < NK) {
            sstore(s ^ 1);
            __syncthreads();
        }
    }

    // epilogue
#pragma unroll
    for (int mi = 0; mi < 4; mi++) {
#pragma unroll
        for (int ni = 0; ni < 4; ni++) {
            long r0 = mb + wm + mi * 16 + g;
            int cI = nb + wn + ni * 8 + q * 2;
            float v0 = acc[mi][ni][0], v1 = acc[mi][ni][1];
            float v2 = acc[mi][ni][2], v3 = acc[mi][ni][3];
            if (GELU) {
                v0 = gelu_tanh_f(v0);
                v1 = gelu_tanh_f(v1);
                v2 = gelu_tanh_f(v2);
                v3 = gelu_tanh_f(v3);
            }
            *(float2*)(C + r0 * N + cI)       = make_float2(v0, v1);
            *(float2*)(C + (r0 + 8) * N + cI) = make_float2(v2, v3);
        }
    }
}

extern "C" void kernel_launch(void* const* d_in, const int* in_sizes, int n_in,
                              void* d_out, int out_size) {
    const float* x  = (const float*)d_in[0];
    const float* w1 = (const float*)d_in[1];
    const float* w2 = (const float*)d_in[2];
    float* out = (float*)d_out;

    float* hbuf = nullptr;
    cudaGetSymbolAddress((void**)&hbuf, g_h);

    cudaFuncSetAttribute(gemm_bf16x3<true>,  cudaFuncAttributeMaxDynamicSharedMemorySize, SMEM_BYTES);
    cudaFuncSetAttribute(gemm_bf16x3<false>, cudaFuncAttributeMaxDynamicSharedMemorySize, SMEM_BYTES);

    dim3 blk(256, 1, 1);
    // GEMM1 + GELU: [T,H] @ [H,F] -> h [T,F], per expert
    gemm_bf16x3<true><<<dim3(F_ / TN, T_ / TM, E_), blk, SMEM_BYTES>>>(
        x, w1, hbuf, T_, F_, H_, (long)T_ * H_, (long)H_ * F_, (long)T_ * F_);
    // GEMM2: h [T,F] @ [F,H] -> out [T,H], per expert
    gemm_bf16x3<false><<<dim3(H_ / TN, T_ / TM, E_), blk, SMEM_BYTES>>>(
        hbuf, w2, out, T_, H_, F_, (long)T_ * F_, (long)F_ * H_, (long)T_ * H_);
}

// round 3
// speedup vs baseline: 2.8129x; 2.8129x over previous
#include <cuda_runtime.h>
#include <cuda_bf16.h>
#include <cstdint>
#include <math.h>

// ============================================================================
// MLP: out[e] = gelu_tanh(x[e] @ w1[e]) @ w2[e]
//   E=8, T=2048, H=1024, F=4096, fp32 in/out.
// bf16x3 split on warp mma.sync (m16n8k16), fp32 acc.  (tcgen05 unavailable:
// harness compiles to compute_103 PTX without the 'a' feature set.)
// Pre-pass: fp32 -> bf16 hi/lo split; weights transposed to K-major [N,K].
// GEMM: CTA 128x128, K-chunk 64, cp.async double buffer, SW128 swizzle,
//       ldmatrix fragment loads, GELU fused into GEMM1 epilogue (bf16 hi/lo).
// ============================================================================

static constexpr int E_ = 8, T_ = 2048, H_ = 1024, F_ = 4096;

// -------- static device scratch (allocation-guard-safe) --------
__device__ __nv_bfloat16 g_xh[(size_t)E_ * T_ * H_];
__device__ __nv_bfloat16 g_xl[(size_t)E_ * T_ * H_];
__device__ __nv_bfloat16 g_w1h[(size_t)E_ * F_ * H_];  // w1^T: [E,F,H]
__device__ __nv_bfloat16 g_w1l[(size_t)E_ * F_ * H_];
__device__ __nv_bfloat16 g_w2h[(size_t)E_ * H_ * F_];  // w2^T: [E,H,F]
__device__ __nv_bfloat16 g_w2l[(size_t)E_ * H_ * F_];
__device__ __nv_bfloat16 g_hh[(size_t)E_ * T_ * F_];   // gelu(x@w1) hi
__device__ __nv_bfloat16 g_hl[(size_t)E_ * T_ * F_];   // gelu(x@w1) lo

// -------- helpers --------
__device__ __forceinline__ uint32_t smem_u32(const void* p) {
    return (uint32_t)__cvta_generic_to_shared(p);
}
__device__ __forceinline__ void cp16(uint32_t s, const void* g) {
    asm volatile("cp.async.cg.shared.global [%0], [%1], 16;\n"
                 :: "r"(s), "l"(__cvta_generic_to_global(g)));
}
__device__ __forceinline__ void cp_commit() {
    asm volatile("cp.async.commit_group;\n" ::: "memory");
}
template <int N> __device__ __forceinline__ void cp_wait() {
    asm volatile("cp.async.wait_group %0;\n" :: "n"(N) : "memory");
}
#define SWZ(x) ((x) ^ (((x) >> 3) & 0x70))

#define LDSM_X4(r0, r1, r2, r3, a)                                          \
    asm volatile("ldmatrix.sync.aligned.m8n8.x4.shared.b16 {%0,%1,%2,%3}, [%4];" \
                 : "=r"(r0), "=r"(r1), "=r"(r2), "=r"(r3) : "r"(a))

__device__ __forceinline__ void mma16816(float* c, const uint32_t* a, const uint32_t* b) {
    asm volatile(
        "mma.sync.aligned.m16n8k16.row.col.f32.bf16.bf16.f32 "
        "{%0,%1,%2,%3}, {%4,%5,%6,%7}, {%8,%9}, {%0,%1,%2,%3};\n"
        : "+f"(c[0]), "+f"(c[1]), "+f"(c[2]), "+f"(c[3])
        : "r"(a[0]), "r"(a[1]), "r"(a[2]), "r"(a[3]), "r"(b[0]), "r"(b[1]));
}

__device__ __forceinline__ float gelu_tanh_f(float x) {
    float inner = 0.7978845608028654f * (x + 0.044715f * x * x * x);
    return 0.5f * x * (1.0f + tanhf(inner));
}

// -------- pre-pass: elementwise fp32 -> bf16 hi/lo --------
__global__ void split_k(const float* __restrict__ in, __nv_bfloat16* __restrict__ hi,
                        __nv_bfloat16* __restrict__ lo, size_t n4) {
    size_t i = (size_t)blockIdx.x * blockDim.x + threadIdx.x;
    if (i >= n4) return;
    float4 v = ((const float4*)in)[i];
    float f[4] = {v.x, v.y, v.z, v.w};
    __nv_bfloat16 h[4], l[4];
#pragma unroll
    for (int j = 0; j < 4; j++) {
        h[j] = __float2bfloat16(f[j]);
        l[j] = __float2bfloat16(f[j] - __bfloat162float(h[j]));
    }
    __nv_bfloat162 h2a = __halves2bfloat162(h[0], h[1]), h2b = __halves2bfloat162(h[2], h[3]);
    __nv_bfloat162 l2a = __halves2bfloat162(l[0], l[1]), l2b = __halves2bfloat162(l[2], l[3]);
    ((uint2*)hi)[i] = make_uint2(*(uint32_t*)&h2a, *(uint32_t*)&h2b);
    ((uint2*)lo)[i] = make_uint2(*(uint32_t*)&l2a, *(uint32_t*)&l2b);
}

// -------- pre-pass: transpose [E,R,C] -> [E,C,R] + split --------
__global__ void tsplit_k(const float* __restrict__ in, __nv_bfloat16* __restrict__ hi,
                         __nv_bfloat16* __restrict__ lo, int R, int C) {
    __shared__ float t[32][33];
    int e = blockIdx.z;
    const float* ip = in + (size_t)e * R * C;
    size_t ob = (size_t)e * R * C;
    int c0 = blockIdx.x * 32, r0 = blockIdx.y * 32;
    for (int j = threadIdx.y; j < 32; j += 8)
        t[j][threadIdx.x] = ip[(size_t)(r0 + j) * C + c0 + threadIdx.x];
    __syncthreads();
    for (int j = threadIdx.y; j < 32; j += 8) {
        float v = t[threadIdx.x][j];
        __nv_bfloat16 h = __float2bfloat16(v);
        __nv_bfloat16 l = __float2bfloat16(v - __bfloat162float(h));
        size_t o = ob + (size_t)(c0 + j) * R + r0 + threadIdx.x;
        hi[o] = h;
        lo[o] = l;
    }
}

// -------- warp-mma GEMM: C[M,N] = A[M,K] @ B[N,K]^T, bf16x3, fp32 acc ------
#define CTA_M 128
#define CTA_N 128
#define CTA_K 64
#define ARR_BYTES (128 * 128)           // 128 rows x 128B (64 bf16)
#define STAGE_BYTES (4 * ARR_BYTES)     // Ah, Al, Bh, Bl  = 64 KB
#define SMEM_TOTAL (2 * STAGE_BYTES)    // double buffer   = 128 KB

template <bool FUSE_GELU>
__global__ __launch_bounds__(256, 1)
void gemm_wm(const __nv_bfloat16* __restrict__ Ah, const __nv_bfloat16* __restrict__ Al,
             const __nv_bfloat16* __restrict__ Bh, const __nv_bfloat16* __restrict__ Bl,
             float* __restrict__ Cf, __nv_bfloat16* __restrict__ Chh,
             __nv_bfloat16* __restrict__ Chl, int M, int N, int K) {
    extern __shared__ __align__(128) char smem[];
    uint32_t sb = smem_u32(smem);
    const int tid = threadIdx.x, warp = tid >> 5, lid = tid & 31;
    const int e = blockIdx.z;
    const int m0 = blockIdx.y * CTA_M, n0 = blockIdx.x * CTA_N;
    const int wm = (warp >> 2) * 64;    // 2 warp rows
    const int wn = (warp & 3) * 32;     // 4 warp cols
    const int g = lid >> 2, q = lid & 3;

    size_t eA = (size_t)e * M * K, eB = (size_t)e * N * K;
    const __nv_bfloat16* gp[4] = {Ah + eA + (size_t)m0 * K, Al + eA + (size_t)m0 * K,
                                  Bh + eB + (size_t)n0 * K, Bl + eB + (size_t)n0 * K};

    float acc[4][4][4];
#pragma unroll
    for (int mi = 0; mi < 4; mi++)
#pragma unroll
        for (int ni = 0; ni < 4; ni++)
#pragma unroll
            for (int k2 = 0; k2 < 4; k2++) acc[mi][ni][k2] = 0.0f;

    auto load_stage = [&](int kt, int s) {
        uint32_t st = sb + s * STAGE_BYTES;
        int k0 = kt * CTA_K;
#pragma unroll
        for (int a = 0; a < 4; a++) {
            uint32_t ab = st + a * ARR_BYTES;
            const __nv_bfloat16* gg = gp[a];
#pragma unroll
            for (int i = 0; i < 4; i++) {
                int c = i * 256 + tid;
                int row = c >> 3, h = c & 7;
                uint32_t rel = (uint32_t)(row * 128 + h * 16);
                cp16(ab + SWZ(rel), gg + (size_t)row * K + k0 + h * 8);
            }
        }
    };

    auto compute = [&](int s) {
        uint32_t st = sb + s * STAGE_BYTES;
        uint32_t aH = st, aL = st + ARR_BYTES;
        uint32_t bH = st + 2 * ARR_BYTES, bL = st + 3 * ARR_BYTES;
#pragma unroll
        for (int kk = 0; kk < CTA_K; kk += 16) {
            uint32_t ah[4][4], al[4][4], bh[4][2], bl[4][2];
            // A fragments: lanes 0-15 -> rows (k first half), 16-31 -> rows (k second)
            {
                int arow = wm + (lid & 15);
                uint32_t acol = (uint32_t)(kk * 2 + (lid >> 4) * 16);
#pragma unroll
                for (int mi = 0; mi < 4; mi++) {
                    uint32_t rel = (uint32_t)((arow + mi * 16) * 128) + acol;
                    uint32_t ad = SWZ(rel);
                    LDSM_X4(ah[mi][0], ah[mi][1], ah[mi][2], ah[mi][3], aH + ad);
                    LDSM_X4(al[mi][0], al[mi][1], al[mi][2], al[mi][3], aL + ad);
                }
            }
            // B fragments: x4 covers 16 n-rows x 16 k -> two n=8 frags
            {
                int brow = wn + ((lid >> 4) & 1) * 8 + (lid & 7);
                uint32_t bcol = (uint32_t)(kk * 2 + ((lid >> 3) & 1) * 16);
#pragma unroll
                for (int nf = 0; nf < 2; nf++) {
                    uint32_t rel = (uint32_t)((brow + nf * 16) * 128) + bcol;
                    uint32_t ad = SWZ(rel);
                    LDSM_X4(bh[nf * 2][0], bh[nf * 2][1], bh[nf * 2 + 1][0], bh[nf * 2 + 1][1],
                            bH + ad);
                    LDSM_X4(bl[nf * 2][0], bl[nf * 2][1], bl[nf * 2 + 1][0], bl[nf * 2 + 1][1],
                            bL + ad);
                }
            }
            // 3 split products; pass-major order -> 16-acc reuse distance
#pragma unroll
            for (int mi = 0; mi < 4; mi++)
#pragma unroll
                for (int ni = 0; ni < 4; ni++) mma16816(acc[mi][ni], ah[mi], bh[ni]);
#pragma unroll
            for (int mi = 0; mi < 4; mi++)
#pragma unroll
                for (int ni = 0; ni < 4; ni++) mma16816(acc[mi][ni], ah[mi], bl[ni]);
#pragma unroll
            for (int mi = 0; mi < 4; mi++)
#pragma unroll
                for (int ni = 0; ni < 4; ni++) mma16816(acc[mi][ni], al[mi], bh[ni]);
        }
    };

    const int NK = K / CTA_K;
    load_stage(0, 0);
    cp_commit();
    if (NK > 1) load_stage(1, 1);
    cp_commit();

    for (int kt = 0; kt < NK; kt++) {
        int s = kt & 1;
        cp_wait<1>();           // group kt complete (one group committed per iter)
        __syncthreads();
        compute(s);
        __syncthreads();        // all warps done with stage s before refill
        if (kt + 2 < NK) load_stage(kt + 2, s);
        cp_commit();            // commit every iter (possibly empty) to keep count
    }

    // ---- epilogue straight from registers ----
#pragma unroll
    for (int mi = 0; mi < 4; mi++) {
#pragma unroll
        for (int ni = 0; ni < 4; ni++) {
            int r = m0 + wm + mi * 16 + g;
            int col = n0 + wn + ni * 8 + q * 2;
            float v0 = acc[mi][ni][0], v1 = acc[mi][ni][1];
            float v2 = acc[mi][ni][2], v3 = acc[mi][ni][3];
            if (FUSE_GELU) {
                v0 = gelu_tanh_f(v0); v1 = gelu_tanh_f(v1);
                v2 = gelu_tanh_f(v2); v3 = gelu_tanh_f(v3);
                __nv_bfloat16 h0 = __float2bfloat16(v0);
                __nv_bfloat16 l0 = __float2bfloat16(v0 - __bfloat162float(h0));
                __nv_bfloat16 h1 = __float2bfloat16(v1);
                __nv_bfloat16 l1 = __float2bfloat16(v1 - __bfloat162float(h1));
                __nv_bfloat16 h2 = __float2bfloat16(v2);
                __nv_bfloat16 l2 = __float2bfloat16(v2 - __bfloat162float(h2));
                __nv_bfloat16 h3 = __float2bfloat16(v3);
                __nv_bfloat16 l3 = __float2bfloat16(v3 - __bfloat162float(h3));
                size_t o0 = ((size_t)e * M + r) * N + col;
                size_t o1 = ((size_t)e * M + r + 8) * N + col;
                __nv_bfloat162 p;
                p = __halves2bfloat162(h0, h1); *(uint32_t*)(Chh + o0) = *(uint32_t*)&p;
                p = __halves2bfloat162(l0, l1); *(uint32_t*)(Chl + o0) = *(uint32_t*)&p;
                p = __halves2bfloat162(h2, h3); *(uint32_t*)(Chh + o1) = *(uint32_t*)&p;
                p = __halves2bfloat162(l2, l3); *(uint32_t*)(Chl + o1) = *(uint32_t*)&p;
            } else {
                size_t o0 = ((size_t)e * M + r) * N + col;
                size_t o1 = ((size_t)e * M + r + 8) * N + col;
                *(float2*)(Cf + o0) = make_float2(v0, v1);
                *(float2*)(Cf + o1) = make_float2(v2, v3);
            }
        }
    }
}

// -------- host launch --------
extern "C" void kernel_launch(void* const* d_in, const int* in_sizes, int n_in,
                              void* d_out, int out_size) {
    const float* x = (const float*)d_in[0];
    const float* w1 = (const float*)d_in[1];
    const float* w2 = (const float*)d_in[2];
    float* out = (float*)d_out;

    __nv_bfloat16 *xh, *xl, *w1h, *w1l, *w2h, *w2l, *hh, *hl;
    cudaGetSymbolAddress((void**)&xh, g_xh);
    cudaGetSymbolAddress((void**)&xl, g_xl);
    cudaGetSymbolAddress((void**)&w1h, g_w1h);
    cudaGetSymbolAddress((void**)&w1l, g_w1l);
    cudaGetSymbolAddress((void**)&w2h, g_w2h);
    cudaGetSymbolAddress((void**)&w2l, g_w2l);
    cudaGetSymbolAddress((void**)&hh, g_hh);
    cudaGetSymbolAddress((void**)&hl, g_hl);

    cudaFuncSetAttribute(gemm_wm<true>, cudaFuncAttributeMaxDynamicSharedMemorySize, SMEM_TOTAL);
    cudaFuncSetAttribute(gemm_wm<false>, cudaFuncAttributeMaxDynamicSharedMemorySize, SMEM_TOTAL);

    // pre-pass: split x; transpose+split weights
    size_t nx4 = (size_t)E_ * T_ * H_ / 4;
    split_k<<<(unsigned)((nx4 + 255) / 256), 256>>>(x, xh, xl, nx4);
    tsplit_k<<<dim3(F_ / 32, H_ / 32, E_), dim3(32, 8)>>>(w1, w1h, w1l, H_, F_);
    tsplit_k<<<dim3(H_ / 32, F_ / 32, E_), dim3(32, 8)>>>(w2, w2h, w2l, F_, H_);

    // GEMM1 + GELU: A=x [T,H], B=w1^T [F,H] -> h bf16 hi/lo [T,F]
    gemm_wm<true><<<dim3(F_ / CTA_N, T_ / CTA_M, E_), 256, SMEM_TOTAL>>>(
        xh, xl, w1h, w1l, nullptr, hh, hl, T_, F_, H_);
    // GEMM2: A=h [T,F], B=w2^T [H,F] -> out fp32 [T,H]
    gemm_wm<false><<<dim3(H_ / CTA_N, T_ / CTA_M, E_), 256, SMEM_TOTAL>>>(
        hh, hl, w2h, w2l, out, nullptr, nullptr, T_, H_, F_);
}

// round 4
// speedup vs baseline: 3.3611x; 1.1949x over previous
#include <cuda_runtime.h>
#include <cuda_bf16.h>
#include <cuda_fp16.h>
#include <cstdint>
#include <math.h>

// ============================================================================
// MLP: out[e] = gelu_tanh(x[e] @ w1[e]) @ w2[e]
//   E=8, T=2048, H=1024, F=4096, fp32 in/out.
// GEMM1: bf16x3 split (x hi/lo, w1 hi/lo -> 3 mma products), gelu fused,
//        output h stored as fp16 single.
// GEMM2: h (fp16) x w2 (fp16 hi/lo) -> 2 mma products, fp32 out.
// Both: warp mma.sync m16n8k16, cp.async 3-stage pipeline (lookahead 2,
//       single barrier/iter), SW128 swizzle, ldmatrix fragments.
// ============================================================================

static constexpr int E_ = 8, T_ = 2048, H_ = 1024, F_ = 4096;

// -------- static device scratch --------
__device__ __nv_bfloat16 g_xh[(size_t)E_ * T_ * H_];
__device__ __nv_bfloat16 g_xl[(size_t)E_ * T_ * H_];
__device__ __nv_bfloat16 g_w1h[(size_t)E_ * F_ * H_];  // w1^T: [E,F,H] bf16 hi
__device__ __nv_bfloat16 g_w1l[(size_t)E_ * F_ * H_];
__device__ __half        g_w2h[(size_t)E_ * H_ * F_];  // w2^T: [E,H,F] fp16 hi
__device__ __half        g_w2l[(size_t)E_ * H_ * F_];
__device__ __half        g_h16[(size_t)E_ * T_ * F_];  // gelu(x@w1) fp16

// -------- helpers --------
__device__ __forceinline__ uint32_t smem_u32(const void* p) {
    return (uint32_t)__cvta_generic_to_shared(p);
}
__device__ __forceinline__ void cp16(uint32_t s, const void* g) {
    asm volatile("cp.async.cg.shared.global [%0], [%1], 16;\n"
                 :: "r"(s), "l"(__cvta_generic_to_global(g)));
}
__device__ __forceinline__ void cp_commit() {
    asm volatile("cp.async.commit_group;\n" ::: "memory");
}
template <int N> __device__ __forceinline__ void cp_wait() {
    asm volatile("cp.async.wait_group %0;\n" :: "n"(N) : "memory");
}
#define SWZ(x) ((x) ^ (((x) >> 3) & 0x70))

#define LDSM_X4(r0, r1, r2, r3, a)                                          \
    asm volatile("ldmatrix.sync.aligned.m8n8.x4.shared.b16 {%0,%1,%2,%3}, [%4];" \
                 : "=r"(r0), "=r"(r1), "=r"(r2), "=r"(r3) : "r"(a))

template <bool FP16>
__device__ __forceinline__ void mma16816(float* c, const uint32_t* a, const uint32_t* b) {
    if (FP16)
        asm volatile(
            "mma.sync.aligned.m16n8k16.row.col.f32.f16.f16.f32 "
            "{%0,%1,%2,%3}, {%4,%5,%6,%7}, {%8,%9}, {%0,%1,%2,%3};\n"
            : "+f"(c[0]), "+f"(c[1]), "+f"(c[2]), "+f"(c[3])
            : "r"(a[0]), "r"(a[1]), "r"(a[2]), "r"(a[3]), "r"(b[0]), "r"(b[1]));
    else
        asm volatile(
            "mma.sync.aligned.m16n8k16.row.col.f32.bf16.bf16.f32 "
            "{%0,%1,%2,%3}, {%4,%5,%6,%7}, {%8,%9}, {%0,%1,%2,%3};\n"
            : "+f"(c[0]), "+f"(c[1]), "+f"(c[2]), "+f"(c[3])
            : "r"(a[0]), "r"(a[1]), "r"(a[2]), "r"(a[3]), "r"(b[0]), "r"(b[1]));
}

__device__ __forceinline__ float gelu_tanh_f(float x) {
    float inner = 0.7978845608028654f * (x + 0.044715f * x * x * x);
    return 0.5f * x * (1.0f + tanhf(inner));
}

// -------- pre-pass: elementwise fp32 -> bf16 hi/lo --------
__global__ void split_k(const float* __restrict__ in, __nv_bfloat16* __restrict__ hi,
                        __nv_bfloat16* __restrict__ lo, size_t n4) {
    size_t i = (size_t)blockIdx.x * blockDim.x + threadIdx.x;
    if (i >= n4) return;
    float4 v = ((const float4*)in)[i];
    float f[4] = {v.x, v.y, v.z, v.w};
    __nv_bfloat16 h[4], l[4];
#pragma unroll
    for (int j = 0; j < 4; j++) {
        h[j] = __float2bfloat16(f[j]);
        l[j] = __float2bfloat16(f[j] - __bfloat162float(h[j]));
    }
    __nv_bfloat162 h2a = __halves2bfloat162(h[0], h[1]), h2b = __halves2bfloat162(h[2], h[3]);
    __nv_bfloat162 l2a = __halves2bfloat162(l[0], l[1]), l2b = __halves2bfloat162(l[2], l[3]);
    ((uint2*)hi)[i] = make_uint2(*(uint32_t*)&h2a, *(uint32_t*)&h2b);
    ((uint2*)lo)[i] = make_uint2(*(uint32_t*)&l2a, *(uint32_t*)&l2b);
}

// -------- pre-pass: transpose [E,R,C] -> [E,C,R] + split (bf16) --------
__global__ void tsplit_bf(const float* __restrict__ in, __nv_bfloat16* __restrict__ hi,
                          __nv_bfloat16* __restrict__ lo, int R, int C) {
    __shared__ float t[32][33];
    int e = blockIdx.z;
    const float* ip = in + (size_t)e * R * C;
    size_t ob = (size_t)e * R * C;
    int c0 = blockIdx.x * 32, r0 = blockIdx.y * 32;
    for (int j = threadIdx.y; j < 32; j += 8)
        t[j][threadIdx.x] = ip[(size_t)(r0 + j) * C + c0 + threadIdx.x];
    __syncthreads();
    for (int j = threadIdx.y; j < 32; j += 8) {
        float v = t[threadIdx.x][j];
        __nv_bfloat16 h = __float2bfloat16(v);
        __nv_bfloat16 l = __float2bfloat16(v - __bfloat162float(h));
        size_t o = ob + (size_t)(c0 + j) * R + r0 + threadIdx.x;
        hi[o] = h;
        lo[o] = l;
    }
}

// -------- pre-pass: transpose + split (fp16) --------
__global__ void tsplit_fp16(const float* __restrict__ in, __half* __restrict__ hi,
                            __half* __restrict__ lo, int R, int C) {
    __shared__ float t[32][33];
    int e = blockIdx.z;
    const float* ip = in + (size_t)e * R * C;
    size_t ob = (size_t)e * R * C;
    int c0 = blockIdx.x * 32, r0 = blockIdx.y * 32;
    for (int j = threadIdx.y; j < 32; j += 8)
        t[j][threadIdx.x] = ip[(size_t)(r0 + j) * C + c0 + threadIdx.x];
    __syncthreads();
    for (int j = threadIdx.y; j < 32; j += 8) {
        float v = t[threadIdx.x][j];
        __half h = __float2half_rn(v);
        __half l = __float2half_rn(v - __half2float(h));
        size_t o = ob + (size_t)(c0 + j) * R + r0 + threadIdx.x;
        hi[o] = h;
        lo[o] = l;
    }
}

// -------- warp-mma GEMM: C[M,N] = A[M,K] @ B[N,K]^T --------
// NPROD==3: A hi/lo + B hi/lo (bf16), products ah*bh, ah*bl, al*bh.
// NPROD==2: A single + B hi/lo (fp16), products a*bh, a*bl.
#define CTA_M 128
#define CTA_N 128
#define CTA_K 64
#define ARR_BYTES (128 * 128)   // 128 rows x 128B (64 x 16-bit)
#define STAGES 3

template <int NPROD, bool FP16, bool FUSE_GELU>
__global__ __launch_bounds__(256, 1)
void gemm_wm(const uint16_t* __restrict__ A0, const uint16_t* __restrict__ A1,
             const uint16_t* __restrict__ B0, const uint16_t* __restrict__ B1,
             float* __restrict__ Cf, __half* __restrict__ Ch,
             int M, int N, int K) {
    constexpr int NA = (NPROD == 3) ? 4 : 3;         // arrays per stage
    constexpr int STAGE_BYTES = NA * ARR_BYTES;
    extern __shared__ __align__(1024) char smem[];
    uint32_t sb = smem_u32(smem);
    const int tid = threadIdx.x, warp = tid >> 5, lid = tid & 31;
    const int e = blockIdx.z;
    const int m0 = blockIdx.y * CTA_M, n0 = blockIdx.x * CTA_N;
    const int wm = (warp >> 2) * 64;    // 2 warp rows
    const int wn = (warp & 3) * 32;     // 4 warp cols
    const int g = lid >> 2, q = lid & 3;

    size_t eA = (size_t)e * M * K, eB = (size_t)e * N * K;
    const uint16_t* gp[4];
    gp[0] = A0 + eA + (size_t)m0 * K;
    if (NPROD == 3) {
        gp[1] = A1 + eA + (size_t)m0 * K;
        gp[2] = B0 + eB + (size_t)n0 * K;
        gp[3] = B1 + eB + (size_t)n0 * K;
    } else {
        gp[1] = B0 + eB + (size_t)n0 * K;
        gp[2] = B1 + eB + (size_t)n0 * K;
    }

    float acc[4][4][4];
#pragma unroll
    for (int mi = 0; mi < 4; mi++)
#pragma unroll
        for (int ni = 0; ni < 4; ni++)
#pragma unroll
            for (int k2 = 0; k2 < 4; k2++) acc[mi][ni][k2] = 0.0f;

    auto load_stage = [&](int kt, int s) {
        uint32_t st = sb + s * STAGE_BYTES;
        int k0 = kt * CTA_K;
#pragma unroll
        for (int a = 0; a < NA; a++) {
            uint32_t ab = st + a * ARR_BYTES;
            const uint16_t* gg = gp[a];
#pragma unroll
            for (int i = 0; i < 4; i++) {
                int c = i * 256 + tid;
                int row = c >> 3, h = c & 7;
                uint32_t rel = (uint32_t)(row * 128 + h * 16);
                cp16(ab + SWZ(rel), gg + (size_t)row * K + k0 + h * 8);
            }
        }
    };

    auto compute = [&](int s) {
        uint32_t st = sb + s * STAGE_BYTES;
        uint32_t aH = st;
        uint32_t aL = st + ARR_BYTES;                       // NPROD==3 only
        uint32_t bH = st + (NA - 2) * ARR_BYTES;
        uint32_t bL = st + (NA - 1) * ARR_BYTES;
#pragma unroll
        for (int kk = 0; kk < CTA_K; kk += 16) {
            uint32_t ah[4][4], al[4][4], bh[4][2], bl[4][2];
            {
                int arow = wm + (lid & 15);
                uint32_t acol = (uint32_t)(kk * 2 + (lid >> 4) * 16);
#pragma unroll
                for (int mi = 0; mi < 4; mi++) {
                    uint32_t rel = (uint32_t)((arow + mi * 16) * 128) + acol;
                    uint32_t ad = SWZ(rel);
                    LDSM_X4(ah[mi][0], ah[mi][1], ah[mi][2], ah[mi][3], aH + ad);
                    if (NPROD == 3)
                        LDSM_X4(al[mi][0], al[mi][1], al[mi][2], al[mi][3], aL + ad);
                }
            }
            {
                int brow = wn + ((lid >> 4) & 1) * 8 + (lid & 7);
                uint32_t bcol = (uint32_t)(kk * 2 + ((lid >> 3) & 1) * 16);
#pragma unroll
                for (int nf = 0; nf < 2; nf++) {
                    uint32_t rel = (uint32_t)((brow + nf * 16) * 128) + bcol;
                    uint32_t ad = SWZ(rel);
                    LDSM_X4(bh[nf * 2][0], bh[nf * 2][1], bh[nf * 2 + 1][0], bh[nf * 2 + 1][1],
                            bH + ad);
                    LDSM_X4(bl[nf * 2][0], bl[nf * 2][1], bl[nf * 2 + 1][0], bl[nf * 2 + 1][1],
                            bL + ad);
                }
            }
#pragma unroll
            for (int mi = 0; mi < 4; mi++)
#pragma unroll
                for (int ni = 0; ni < 4; ni++) mma16816<FP16>(acc[mi][ni], ah[mi], bh[ni]);
#pragma unroll
            for (int mi = 0; mi < 4; mi++)
#pragma unroll
                for (int ni = 0; ni < 4; ni++) mma16816<FP16>(acc[mi][ni], ah[mi], bl[ni]);
            if (NPROD == 3) {
#pragma unroll
                for (int mi = 0; mi < 4; mi++)
#pragma unroll
                    for (int ni = 0; ni < 4; ni++) mma16816<FP16>(acc[mi][ni], al[mi], bh[ni]);
            }
        }
    };

    const int NK = K / CTA_K;
    // prologue: 2 stages in flight
    load_stage(0, 0);
    cp_commit();
    load_stage(1, 1);
    cp_commit();

    int s = 0, s2 = 2;  // s = stage of kt, s2 = stage of kt+2
    for (int kt = 0; kt < NK; kt++) {
        cp_wait<1>();           // group kt complete
        __syncthreads();        // data visible to all; stage s2 free (compute(kt-1) done)
        if (kt + 2 < NK) load_stage(kt + 2, s2);
        cp_commit();            // always commit (possibly empty) to keep group count
        compute(s);
        s = (s == 2) ? 0 : s + 1;
        s2 = (s2 == 2) ? 0 : s2 + 1;
    }

    // ---- epilogue ----
#pragma unroll
    for (int mi = 0; mi < 4; mi++) {
#pragma unroll
        for (int ni = 0; ni < 4; ni++) {
            int r = m0 + wm + mi * 16 + g;
            int col = n0 + wn + ni * 8 + q * 2;
            size_t o0 = ((size_t)e * M + r) * N + col;
            size_t o1 = o0 + (size_t)8 * N;
            float v0 = acc[mi][ni][0], v1 = acc[mi][ni][1];
            float v2 = acc[mi][ni][2], v3 = acc[mi][ni][3];
            if (FUSE_GELU) {
                v0 = gelu_tanh_f(v0); v1 = gelu_tanh_f(v1);
                v2 = gelu_tanh_f(v2); v3 = gelu_tanh_f(v3);
                __half2 p0 = __floats2half2_rn(v0, v1);
                __half2 p1 = __floats2half2_rn(v2, v3);
                *(__half2*)(Ch + o0) = p0;
                *(__half2*)(Ch + o1) = p1;
            } else {
                *(float2*)(Cf + o0) = make_float2(v0, v1);
                *(float2*)(Cf + o1) = make_float2(v2, v3);
            }
        }
    }
}

// -------- host launch --------
extern "C" void kernel_launch(void* const* d_in, const int* in_sizes, int n_in,
                              void* d_out, int out_size) {
    const float* x = (const float*)d_in[0];
    const float* w1 = (const float*)d_in[1];
    const float* w2 = (const float*)d_in[2];
    float* out = (float*)d_out;

    __nv_bfloat16 *xh, *xl, *w1h, *w1l;
    __half *w2h, *w2l, *h16;
    cudaGetSymbolAddress((void**)&xh, g_xh);
    cudaGetSymbolAddress((void**)&xl, g_xl);
    cudaGetSymbolAddress((void**)&w1h, g_w1h);
    cudaGetSymbolAddress((void**)&w1l, g_w1l);
    cudaGetSymbolAddress((void**)&w2h, g_w2h);
    cudaGetSymbolAddress((void**)&w2l, g_w2l);
    cudaGetSymbolAddress((void**)&h16, g_h16);

    constexpr int SMEM1 = STAGES * 4 * ARR_BYTES;   // 192 KB
    constexpr int SMEM2 = STAGES * 3 * ARR_BYTES;   // 144 KB
    cudaFuncSetAttribute(gemm_wm<3, false, true>, cudaFuncAttributeMaxDynamicSharedMemorySize, SMEM1);
    cudaFuncSetAttribute(gemm_wm<2, true, false>, cudaFuncAttributeMaxDynamicSharedMemorySize, SMEM2);

    // pre-pass
    size_t nx4 = (size_t)E_ * T_ * H_ / 4;
    split_k<<<(unsigned)((nx4 + 255) / 256), 256>>>(x, xh, xl, nx4);
    tsplit_bf<<<dim3(F_ / 32, H_ / 32, E_), dim3(32, 8)>>>(w1, w1h, w1l, H_, F_);
    tsplit_fp16<<<dim3(H_ / 32, F_ / 32, E_), dim3(32, 8)>>>(w2, w2h, w2l, F_, H_);

    // GEMM1 + GELU: A=x bf16 hi/lo [T,H], B=w1^T bf16 hi/lo [F,H] -> h fp16 [T,F]
    gemm_wm<3, false, true><<<dim3(F_ / CTA_N, T_ / CTA_M, E_), 256, SMEM1>>>(
        (const uint16_t*)xh, (const uint16_t*)xl,
        (const uint16_t*)w1h, (const uint16_t*)w1l,
        nullptr, h16, T_, F_, H_);
    // GEMM2: A=h fp16 [T,F], B=w2^T fp16 hi/lo [H,F] -> out fp32 [T,H]
    gemm_wm<2, true, false><<<dim3(H_ / CTA_N, T_ / CTA_M, E_), 256, SMEM2>>>(
        (const uint16_t*)h16, nullptr,
        (const uint16_t*)w2h, (const uint16_t*)w2l,
        out, nullptr, T_, H_, F_);
}

// round 5
// speedup vs baseline: 4.0446x; 1.2034x over previous
#include <cuda_runtime.h>
#include <cuda_bf16.h>
#include <cuda_fp16.h>
#include <cstdint>
#include <math.h>

// ============================================================================
// MLP: out[e] = gelu_tanh(x[e] @ w1[e]) @ w2[e]
//   E=8, T=2048, H=1024, F=4096, fp32 in/out.
// Both GEMMs: 2-product fp16 split (A fp16 single, B fp16 hi/lo), fp32 acc.
//   GEMM1: A=x(fp16), B=w1^T hi/lo -> h fp16 (gelu fused)
//   GEMM2: A=h(fp16), B=w2^T hi/lo -> out fp32
// warp mma.sync m16n8k16, cp.async 4-stage pipeline (lookahead 3, one
// barrier/iter), SW128 swizzle, ldmatrix fragments.
// Error model (calibrated R4): 2.08e-4 per fp16 rounding event; two events
// -> ~2.9e-4 total, threshold 1e-3.
// ============================================================================

static constexpr int E_ = 8, T_ = 2048, H_ = 1024, F_ = 4096;

// -------- static device scratch --------
__device__ __half g_x16[(size_t)E_ * T_ * H_];        // x fp16
__device__ __half g_w1h[(size_t)E_ * F_ * H_];        // w1^T: [E,F,H] fp16 hi
__device__ __half g_w1l[(size_t)E_ * F_ * H_];
__device__ __half g_w2h[(size_t)E_ * H_ * F_];        // w2^T: [E,H,F] fp16 hi
__device__ __half g_w2l[(size_t)E_ * H_ * F_];
__device__ __half g_h16[(size_t)E_ * T_ * F_];        // gelu(x@w1) fp16

// -------- helpers --------
__device__ __forceinline__ uint32_t smem_u32(const void* p) {
    return (uint32_t)__cvta_generic_to_shared(p);
}
__device__ __forceinline__ void cp16(uint32_t s, const void* g) {
    asm volatile("cp.async.cg.shared.global [%0], [%1], 16;\n"
                 :: "r"(s), "l"(__cvta_generic_to_global(g)));
}
__device__ __forceinline__ void cp_commit() {
    asm volatile("cp.async.commit_group;\n" ::: "memory");
}
template <int N> __device__ __forceinline__ void cp_wait() {
    asm volatile("cp.async.wait_group %0;\n" :: "n"(N) : "memory");
}
#define SWZ(x) ((x) ^ (((x) >> 3) & 0x70))

#define LDSM_X4(r0, r1, r2, r3, a)                                          \
    asm volatile("ldmatrix.sync.aligned.m8n8.x4.shared.b16 {%0,%1,%2,%3}, [%4];" \
                 : "=r"(r0), "=r"(r1), "=r"(r2), "=r"(r3) : "r"(a))

__device__ __forceinline__ void mma16816(float* c, const uint32_t* a, const uint32_t* b) {
    asm volatile(
        "mma.sync.aligned.m16n8k16.row.col.f32.f16.f16.f32 "
        "{%0,%1,%2,%3}, {%4,%5,%6,%7}, {%8,%9}, {%0,%1,%2,%3};\n"
        : "+f"(c[0]), "+f"(c[1]), "+f"(c[2]), "+f"(c[3])
        : "r"(a[0]), "r"(a[1]), "r"(a[2]), "r"(a[3]), "r"(b[0]), "r"(b[1]));
}

__device__ __forceinline__ float gelu_tanh_f(float x) {
    float inner = 0.7978845608028654f * (x + 0.044715f * x * x * x);
    return 0.5f * x * (1.0f + tanhf(inner));
}

// -------- pre-pass: fp32 -> fp16 convert (x) --------
__global__ void conv16_k(const float* __restrict__ in, __half* __restrict__ o, size_t n4) {
    size_t i = (size_t)blockIdx.x * blockDim.x + threadIdx.x;
    if (i >= n4) return;
    float4 v = ((const float4*)in)[i];
    __half2 a = __floats2half2_rn(v.x, v.y);
    __half2 b = __floats2half2_rn(v.z, v.w);
    ((uint2*)o)[i] = make_uint2(*(uint32_t*)&a, *(uint32_t*)&b);
}

// -------- pre-pass: transpose [E,R,C] -> [E,C,R] + fp16 hi/lo split --------
// paired 32-bit stores (two consecutive r per thread)
__global__ void tsplit16(const float* __restrict__ in, __half* __restrict__ hi,
                         __half* __restrict__ lo, int R, int C) {
    __shared__ float t[32][33];  // t[r_local][c_local]
    int e = blockIdx.z;
    const float* ip = in + (size_t)e * R * C;
    size_t ob = (size_t)e * R * C;
    int c0 = blockIdx.x * 32, r0 = blockIdx.y * 32;
    int tx = threadIdx.x, ty = threadIdx.y;
    for (int j = ty; j < 32; j += 8)
        t[j][tx] = ip[(size_t)(r0 + j) * C + c0 + tx];
    __syncthreads();
#pragma unroll
    for (int it = 0; it < 2; it++) {
        int cc = it * 16 + ty * 2 + (tx >> 4);   // c_local
        int rr = (tx & 15) * 2;                  // r_local (pair)
        float v0 = t[rr][cc], v1 = t[rr + 1][cc];
        __half h0 = __float2half_rn(v0), h1 = __float2half_rn(v1);
        __half l0 = __float2half_rn(v0 - __half2float(h0));
        __half l1 = __float2half_rn(v1 - __half2float(h1));
        size_t o = ob + (size_t)(c0 + cc) * R + r0 + rr;
        __half2 hp = __halves2half2(h0, h1), lp = __halves2half2(l0, l1);
        *(uint32_t*)(hi + o) = *(uint32_t*)&hp;
        *(uint32_t*)(lo + o) = *(uint32_t*)&lp;
    }
}

// -------- warp-mma GEMM: C[M,N] = A[M,K] @ B[N,K]^T, 2 fp16 products ------
#define CTA_M 128
#define CTA_N 128
#define CTA_K 64
#define ARR_BYTES (128 * 128)       // 128 rows x 128B (64 halves)
#define STAGES 4
#define STAGE_BYTES (3 * ARR_BYTES) // A, Bh, Bl = 48 KB
#define SMEM_TOTAL (STAGES * STAGE_BYTES)  // 192 KB

template <bool FUSE_GELU>
__global__ __launch_bounds__(256, 1)
void gemm_wm(const __half* __restrict__ A0, const __half* __restrict__ B0,
             const __half* __restrict__ B1, float* __restrict__ Cf,
             __half* __restrict__ Ch, int M, int N, int K) {
    extern __shared__ __align__(1024) char smem[];
    uint32_t sb = smem_u32(smem);
    const int tid = threadIdx.x, warp = tid >> 5, lid = tid & 31;
    const int e = blockIdx.z;
    const int m0 = blockIdx.y * CTA_M, n0 = blockIdx.x * CTA_N;
    const int wm = (warp >> 2) * 64;
    const int wn = (warp & 3) * 32;
    const int g = lid >> 2, q = lid & 3;

    size_t eA = (size_t)e * M * K, eB = (size_t)e * N * K;
    const __half* gp[3] = {A0 + eA + (size_t)m0 * K,
                           B0 + eB + (size_t)n0 * K,
                           B1 + eB + (size_t)n0 * K};

    float acc[4][4][4];
#pragma unroll
    for (int mi = 0; mi < 4; mi++)
#pragma unroll
        for (int ni = 0; ni < 4; ni++)
#pragma unroll
            for (int k2 = 0; k2 < 4; k2++) acc[mi][ni][k2] = 0.0f;

    auto load_stage = [&](int kt, int s) {
        uint32_t st = sb + s * STAGE_BYTES;
        int k0 = kt * CTA_K;
#pragma unroll
        for (int a = 0; a < 3; a++) {
            uint32_t ab = st + a * ARR_BYTES;
            const __half* gg = gp[a];
#pragma unroll
            for (int i = 0; i < 4; i++) {
                int c = i * 256 + tid;
                int row = c >> 3, h = c & 7;
                uint32_t rel = (uint32_t)(row * 128 + h * 16);
                cp16(ab + SWZ(rel), gg + (size_t)row * K + k0 + h * 8);
            }
        }
    };

    auto compute = [&](int s) {
        uint32_t st = sb + s * STAGE_BYTES;
        uint32_t aA = st;
        uint32_t bH = st + ARR_BYTES, bL = st + 2 * ARR_BYTES;
#pragma unroll
        for (int kk = 0; kk < CTA_K; kk += 16) {
            uint32_t av[4][4], bh[4][2], bl[4][2];
            {
                int arow = wm + (lid & 15);
                uint32_t acol = (uint32_t)(kk * 2 + (lid >> 4) * 16);
#pragma unroll
                for (int mi = 0; mi < 4; mi++) {
                    uint32_t rel = (uint32_t)((arow + mi * 16) * 128) + acol;
                    uint32_t ad = SWZ(rel);
                    LDSM_X4(av[mi][0], av[mi][1], av[mi][2], av[mi][3], aA + ad);
                }
            }
            {
                int brow = wn + ((lid >> 4) & 1) * 8 + (lid & 7);
                uint32_t bcol = (uint32_t)(kk * 2 + ((lid >> 3) & 1) * 16);
#pragma unroll
                for (int nf = 0; nf < 2; nf++) {
                    uint32_t rel = (uint32_t)((brow + nf * 16) * 128) + bcol;
                    uint32_t ad = SWZ(rel);
                    LDSM_X4(bh[nf * 2][0], bh[nf * 2][1], bh[nf * 2 + 1][0], bh[nf * 2 + 1][1],
                            bH + ad);
                    LDSM_X4(bl[nf * 2][0], bl[nf * 2][1], bl[nf * 2 + 1][0], bl[nf * 2 + 1][1],
                            bL + ad);
                }
            }
#pragma unroll
            for (int mi = 0; mi < 4; mi++)
#pragma unroll
                for (int ni = 0; ni < 4; ni++) mma16816(acc[mi][ni], av[mi], bh[ni]);
#pragma unroll
            for (int mi = 0; mi < 4; mi++)
#pragma unroll
                for (int ni = 0; ni < 4; ni++) mma16816(acc[mi][ni], av[mi], bl[ni]);
        }
    };

    const int NK = K / CTA_K;
    load_stage(0, 0);
    cp_commit();
    load_stage(1, 1);
    cp_commit();
    load_stage(2, 2);
    cp_commit();

    int s = 0, s3 = 3;
    for (int kt = 0; kt < NK; kt++) {
        cp_wait<2>();           // group kt complete (3 in flight, one commit/iter)
        __syncthreads();        // stage s data visible; stage s3 free (compute(kt-1) done)
        if (kt + 3 < NK) load_stage(kt + 3, s3);
        cp_commit();            // commit every iter (possibly empty) to keep count
        compute(s);
        s = (s + 1) & 3;
        s3 = (s3 + 1) & 3;
    }

    // ---- epilogue ----
#pragma unroll
    for (int mi = 0; mi < 4; mi++) {
#pragma unroll
        for (int ni = 0; ni < 4; ni++) {
            int r = m0 + wm + mi * 16 + g;
            int col = n0 + wn + ni * 8 + q * 2;
            size_t o0 = ((size_t)e * M + r) * N + col;
            size_t o1 = o0 + (size_t)8 * N;
            float v0 = acc[mi][ni][0], v1 = acc[mi][ni][1];
            float v2 = acc[mi][ni][2], v3 = acc[mi][ni][3];
            if (FUSE_GELU) {
                v0 = gelu_tanh_f(v0); v1 = gelu_tanh_f(v1);
                v2 = gelu_tanh_f(v2); v3 = gelu_tanh_f(v3);
                __half2 p0 = __floats2half2_rn(v0, v1);
                __half2 p1 = __floats2half2_rn(v2, v3);
                *(__half2*)(Ch + o0) = p0;
                *(__half2*)(Ch + o1) = p1;
            } else {
                *(float2*)(Cf + o0) = make_float2(v0, v1);
                *(float2*)(Cf + o1) = make_float2(v2, v3);
            }
        }
    }
}

// -------- host launch --------
extern "C" void kernel_launch(void* const* d_in, const int* in_sizes, int n_in,
                              void* d_out, int out_size) {
    const float* x = (const float*)d_in[0];
    const float* w1 = (const float*)d_in[1];
    const float* w2 = (const float*)d_in[2];
    float* out = (float*)d_out;

    __half *x16, *w1h, *w1l, *w2h, *w2l, *h16;
    cudaGetSymbolAddress((void**)&x16, g_x16);
    cudaGetSymbolAddress((void**)&w1h, g_w1h);
    cudaGetSymbolAddress((void**)&w1l, g_w1l);
    cudaGetSymbolAddress((void**)&w2h, g_w2h);
    cudaGetSymbolAddress((void**)&w2l, g_w2l);
    cudaGetSymbolAddress((void**)&h16, g_h16);

    cudaFuncSetAttribute(gemm_wm<true>, cudaFuncAttributeMaxDynamicSharedMemorySize, SMEM_TOTAL);
    cudaFuncSetAttribute(gemm_wm<false>, cudaFuncAttributeMaxDynamicSharedMemorySize, SMEM_TOTAL);

    // pre-pass
    size_t nx4 = (size_t)E_ * T_ * H_ / 4;
    conv16_k<<<(unsigned)((nx4 + 255) / 256), 256>>>(x, x16, nx4);
    tsplit16<<<dim3(F_ / 32, H_ / 32, E_), dim3(32, 8)>>>(w1, w1h, w1l, H_, F_);
    tsplit16<<<dim3(H_ / 32, F_ / 32, E_), dim3(32, 8)>>>(w2, w2h, w2l, F_, H_);

    // GEMM1 + GELU: A=x fp16 [T,H], B=w1^T fp16 hi/lo [F,H] -> h fp16 [T,F]
    gemm_wm<true><<<dim3(F_ / CTA_N, T_ / CTA_M, E_), 256, SMEM_TOTAL>>>(
        x16, w1h, w1l, nullptr, h16, T_, F_, H_);
    // GEMM2: A=h fp16 [T,F], B=w2^T fp16 hi/lo [H,F] -> out fp32 [T,H]
    gemm_wm<false><<<dim3(H_ / CTA_N, T_ / CTA_M, E_), 256, SMEM_TOTAL>>>(
        h16, w2h, w2l, out, nullptr, T_, H_, F_);
}